// round 3
// baseline (speedup 1.0000x reference)
#include <cuda_runtime.h>

#define CC 64
#define TT 256
#define VV 25
#define NN 128
#define TC 16              /* t per block */
#define POS 400            /* TC*VV */
#define NPOS 819200.0f     /* NN*TT*VV */
#define NCHUNK 32          /* 64 c / 2 per chunk */
#define SMEMSZ 230400      /* xs 102400 + hs 102400 + Ws 25600 bytes */

// Folded parameters / stats (device globals: no runtime allocation)
__device__ __align__(16) float g_W[VV * CC * CC];    // [v][c][o]
__device__ __align__(16) float g_W2[VV * CC * CC];   // BN+residual folded
__device__ __align__(16) float g_B[CC];
__device__ __align__(16) float g_B2[CC];
__device__ float g_sum[CC];
__device__ float g_sumsq[CC];
__device__ float g_scale[CC];
__device__ float g_shift[CC];

typedef unsigned long long ull;

__device__ __forceinline__ void ffma2(ull& d, ull a, ull b) {
    asm("fma.rn.f32x2 %0, %1, %2, %0;" : "+l"(d) : "l"(a), "l"(b));
}
__device__ __forceinline__ ull packrep(float v) {
    ull r; asm("mov.b64 %0, {%1,%1};" : "=l"(r) : "f"(v)); return r;
}
__device__ __forceinline__ ull pack2(float a, float b) {
    ull r; asm("mov.b64 %0, {%1,%2};" : "=l"(r) : "f"(a), "f"(b)); return r;
}
__device__ __forceinline__ void unpack2(ull p, float& a, float& b) {
    asm("mov.b64 {%0,%1}, %2;" : "=f"(a), "=f"(b) : "l"(p));
}

// ---------------------------------------------------------------------------
// k0: softmax rows sum to 1 -> entire attention path collapses to per-(i,v)
// constants s_i[v] = 1 + sum_w (A+GA)[i,v,w]. Fold into per-vertex weights:
// W[v][c][o] = sum_i s_i[v] * g_w[i][o][c], B[o] = sum_i g_b[i][o].
// ---------------------------------------------------------------------------
__global__ void k0(const float* __restrict__ A, const float* __restrict__ GA,
                   const float* __restrict__ gw, const float* __restrict__ gb) {
    __shared__ float s_sh[3 * 25];
    int tid = threadIdx.x;
    if (tid < CC) {
        g_sum[tid] = 0.f;
        g_sumsq[tid] = 0.f;
        float b = 0.f;
        for (int i = 0; i < 3; i++) b += gb[i * CC + tid];
        g_B[tid] = b;
    }
    if (tid < 75) {
        const float* a = A + tid * 25;
        const float* g = GA + tid * 25;
        float s = 1.f;
        for (int w = 0; w < 25; w++) s += a[w] + g[w];
        s_sh[tid] = s;
    }
    __syncthreads();
    for (int idx = tid; idx < VV * CC * CC; idx += blockDim.x) {
        int v = idx >> 12;
        int c = (idx >> 6) & 63;
        int o = idx & 63;
        float w = 0.f;
        for (int i = 0; i < 3; i++) w += s_sh[i * 25 + v] * gw[(i * CC + o) * CC + c];
        g_W[idx] = w;
    }
}

// ---------------------------------------------------------------------------
// GEMM pass. Block=(tc,n), 512 threads, 16 warps. lane=(t in 0..15, o-half).
// Warp handles v=warp and v=warp+16 (if <25): acc = 2 x 16 packed f32x2.
// x tile staged once (xs[64][400]); W streamed through a double-buffered
// cp.async smem pipeline in 2-channel chunks, consumed via LDS.128.
// MODE 0: accumulate per-channel sum/sumsq of hidden (discard hidden).
// MODE 1: weights already BN+residual-folded; write out = relu(h) via a
//         conflict-free smem transpose, fully coalesced float4 stores.
// ---------------------------------------------------------------------------
template <int MODE>
__global__ void __launch_bounds__(512, 1) gemm_pass(const float* __restrict__ x,
                                                    float* __restrict__ out) {
    extern __shared__ float smem[];
    float* xs = smem;            // 25600 floats: [c][400]
    float* hs = smem + 25600;    // 25600 floats: [o][400]
    float* Wsm = smem + 51200;   // 6400 floats: 2 bufs x [25][2][64]

    const float* Wg = MODE ? g_W2 : g_W;
    const float* Bg = MODE ? g_B2 : g_B;

    int tid = threadIdx.x;
    int tc = blockIdx.x, n = blockIdx.y;

    // stage x tile (coalesced float4)
    const float4* src4 = (const float4*)(x + (size_t)n * CC * TT * VV + tc * POS);
    float4* xs4 = (float4*)xs;
    for (int e = tid; e < CC * 100; e += 512) {
        int c = e / 100, q = e % 100;
        xs4[e] = src4[c * 1600 + q];
    }

    // weight chunk staging via cp.async (chunk cc covers c = 2cc, 2cc+1)
    auto stageW = [&](int cc, int b) {
        unsigned dbase = (unsigned)__cvta_generic_to_shared(Wsm + b * 3200);
        const char* sbase = (const char*)Wg;
        for (int e = tid; e < 800; e += 512) {
            int v = e >> 5, r = e & 31, cl = r >> 4, o4 = r & 15;
            unsigned d = dbase + (unsigned)((v * 32 + cl * 16 + o4) * 16);
            const char* s = sbase + (size_t)(v * 1024 + (2 * cc + cl) * 16 + o4) * 16;
            asm volatile("cp.async.ca.shared.global [%0], [%1], 16;" :: "r"(d), "l"(s));
        }
        asm volatile("cp.async.commit_group;");
    };
    stageW(0, 0);

    int warp = tid >> 5, lane = tid & 31;
    int t = lane & 15, half = lane >> 4;
    int v0 = warp, v1 = warp + 16;
    bool has1 = (v1 < VV);

    ull acc0[16], acc1[16];
#pragma unroll
    for (int j = 0; j < 16; j++) {
        float2 bb = ((const float2*)Bg)[half * 16 + j];
        acc0[j] = pack2(bb.x, bb.y);
        acc1[j] = acc0[j];
    }

    for (int cc = 0; cc < NCHUNK; cc++) {
        __syncthreads();                 // prev compute done; next buf free
        if (cc + 1 < NCHUNK) {
            stageW(cc + 1, (cc + 1) & 1);
            asm volatile("cp.async.wait_group 1;");
        } else {
            asm volatile("cp.async.wait_group 0;");
        }
        __syncthreads();                 // chunk cc visible to all

        const float* wb = Wsm + (cc & 1) * 3200;
#pragma unroll
        for (int cl = 0; cl < 2; cl++) {
            int c = 2 * cc + cl;
            const float* xc = xs + c * POS + t * VV;
            {
                ull x2 = packrep(xc[v0]);
                const ulonglong2* wr =
                    (const ulonglong2*)(wb + v0 * 128 + cl * 64 + half * 32);
#pragma unroll
                for (int j = 0; j < 8; j++) {
                    ulonglong2 w = wr[j];
                    ffma2(acc0[2 * j], w.x, x2);
                    ffma2(acc0[2 * j + 1], w.y, x2);
                }
            }
            if (has1) {
                ull x2 = packrep(xc[v1]);
                const ulonglong2* wr =
                    (const ulonglong2*)(wb + v1 * 128 + cl * 64 + half * 32);
#pragma unroll
                for (int j = 0; j < 8; j++) {
                    ulonglong2 w = wr[j];
                    ffma2(acc1[2 * j], w.x, x2);
                    ffma2(acc1[2 * j + 1], w.y, x2);
                }
            }
        }
    }

    // dump accs into hs[o][pos], pos = t*25+v (stride-25: conflict-light)
#pragma unroll
    for (int j = 0; j < 16; j++) {
        float h0, h1;
        unpack2(acc0[j], h0, h1);
        int o = half * 32 + 2 * j;
        hs[o * POS + t * VV + v0] = h0;
        hs[(o + 1) * POS + t * VV + v0] = h1;
    }
    if (has1) {
#pragma unroll
        for (int j = 0; j < 16; j++) {
            float h0, h1;
            unpack2(acc1[j], h0, h1);
            int o = half * 32 + 2 * j;
            hs[o * POS + t * VV + v1] = h0;
            hs[(o + 1) * POS + t * VV + v1] = h1;
        }
    }
    __syncthreads();

    if (MODE == 0) {
        // per-channel partial sums: 8 threads per o, shfl-combine, 2 REDs each
        int o = tid >> 3, jj = tid & 7;
        const float* row = hs + o * POS;
        float s = 0.f, q = 0.f;
        for (int p = jj; p < POS; p += 8) {
            float val = row[p];
            s += val;
            q += val * val;
        }
#pragma unroll
        for (int d = 4; d; d >>= 1) {
            s += __shfl_xor_sync(0xffffffffu, s, d);
            q += __shfl_xor_sync(0xffffffffu, q, d);
        }
        if (jj == 0) {
            atomicAdd(&g_sum[o], s);
            atomicAdd(&g_sumsq[o], q);
        }
    } else {
        // coalesced relu store (BN + residual already folded into W2/B2)
        float4* out4 = (float4*)(out + (size_t)n * CC * TT * VV + tc * POS);
        const float4* hs4 = (const float4*)hs;
        for (int e = tid; e < CC * 100; e += 512) {
            int o = e / 100, q = e % 100;
            float4 h = hs4[e];
            h.x = fmaxf(h.x, 0.f);
            h.y = fmaxf(h.y, 0.f);
            h.z = fmaxf(h.z, 0.f);
            h.w = fmaxf(h.w, 0.f);
            out4[o * 1600 + q] = h;
        }
    }
}

// ---------------------------------------------------------------------------
// kbn_s: training-mode biased-var BN folded to per-channel scale/shift.
// ---------------------------------------------------------------------------
__global__ void kbn_s(const float* __restrict__ gamma, const float* __restrict__ beta) {
    int o = threadIdx.x;
    if (o < CC) {
        float m = g_sum[o] * (1.0f / NPOS);
        float var = g_sumsq[o] * (1.0f / NPOS) - m * m;
        float r = rsqrtf(var + 1e-5f);
        g_scale[o] = gamma[o] * r;
        g_shift[o] = beta[o] - m * gamma[o] * r;
    }
}

// ---------------------------------------------------------------------------
// kfold: W2 = W*scale + I (identity residual), B2 = B*scale + shift.
// ---------------------------------------------------------------------------
__global__ void kfold() {
    int idx = blockIdx.x * blockDim.x + threadIdx.x;
    if (idx < VV * CC * CC) {
        int c = (idx >> 6) & 63;
        int o = idx & 63;
        g_W2[idx] = g_W[idx] * g_scale[o] + ((c == o) ? 1.0f : 0.0f);
    }
    if (idx < CC) g_B2[idx] = g_B[idx] * g_scale[idx] + g_shift[idx];
}

extern "C" void kernel_launch(void* const* d_in, const int* in_sizes, int n_in,
                              void* d_out, int out_size) {
    const float* x     = (const float*)d_in[0];
    const float* A     = (const float*)d_in[1];
    const float* GA    = (const float*)d_in[2];
    const float* gw    = (const float*)d_in[7];
    const float* gb    = (const float*)d_in[8];
    const float* gamma = (const float*)d_in[9];
    const float* beta  = (const float*)d_in[10];
    float* out = (float*)d_out;
    (void)in_sizes; (void)n_in; (void)out_size;

    cudaFuncSetAttribute(gemm_pass<0>, cudaFuncAttributeMaxDynamicSharedMemorySize, SMEMSZ);
    cudaFuncSetAttribute(gemm_pass<1>, cudaFuncAttributeMaxDynamicSharedMemorySize, SMEMSZ);

    dim3 grid(TT / TC, NN);
    k0<<<1, 256>>>(A, GA, gw, gb);
    gemm_pass<0><<<grid, 512, SMEMSZ>>>(x, out);
    kbn_s<<<1, 64>>>(gamma, beta);
    kfold<<<100, 1024>>>();
    gemm_pass<1><<<grid, 512, SMEMSZ>>>(x, out);
}

// round 4
// speedup vs baseline: 1.5034x; 1.5034x over previous
#include <cuda_runtime.h>

#define CC 64
#define TT 256
#define VV 25
#define NN 128
#define TC 16
#define POS 400            /* TC*VV */
#define XROW 416           /* TC*26 padded row per channel */
#define NPOS 819200.0f
#define NPAIR 13           /* ceil(25/2) vertex pairs; pair 12 = (24, dummy) */
#define NTASK 26           /* NPAIR * 2 o-halves */
#define NW 13              /* warps per block */
#define NTHR 416
#define HSTR 65            /* hs row stride (conflict-free) */
#define XS_BYTES (CC * XROW * 4)      /* 106496 */
#define HS_BYTES (POS * HSTR * 4)     /* 104000 */
#define SM1 (XS_BYTES + 512)
#define SM2 (XS_BYTES + HS_BYTES)

typedef unsigned long long ull;

// Folded parameters / stats (device globals: no runtime allocation)
__device__ __align__(16) float2 g_Wp[NPAIR * CC * CC];   // [p][c][o] = {W[2p,c,o], W[2p+1,c,o]}
__device__ __align__(16) float2 g_Wp2[NPAIR * CC * CC];  // BN+identity-residual folded
__device__ __align__(16) float g_B[CC];
__device__ __align__(16) float g_B2[CC];
__device__ float g_s[3 * 25];
__device__ float g_sum[CC];
__device__ float g_sumsq[CC];
__device__ float g_scale[CC];
__device__ float g_shift[CC];

__device__ __forceinline__ void ffma2(ull& d, ull a, ull b) {
    asm("fma.rn.f32x2 %0, %1, %2, %0;" : "+l"(d) : "l"(a), "l"(b));
}
__device__ __forceinline__ ull packrep(float v) {
    ull r; asm("mov.b64 %0, {%1,%1};" : "=l"(r) : "f"(v)); return r;
}
__device__ __forceinline__ void unpack2(ull p, float& a, float& b) {
    asm("mov.b64 {%0,%1}, %2;" : "=f"(a), "=f"(b) : "l"(p));
}

// ---------------------------------------------------------------------------
// k0: softmax rows sum to 1 -> attention path collapses to s_i[v] =
// 1 + sum_w (A+GA)[i,v,w]. Build vertex-PAIRED weights
// g_Wp[p][c][o] = {sum_i s_i[2p] gw[i,o,c], sum_i s_i[2p+1] gw[i,o,c]}
// (pair 12 second lane = 0). Also B, g_s, and zero the stat accumulators.
// ---------------------------------------------------------------------------
__global__ void k0(const float* __restrict__ A, const float* __restrict__ GA,
                   const float* __restrict__ gw, const float* __restrict__ gb) {
    __shared__ float s_sh[75];
    int tid = threadIdx.x;
    if (tid < 75) {
        const float* a = A + tid * 25;
        const float* g = GA + tid * 25;
        float s = 1.f;
        for (int w = 0; w < 25; w++) s += a[w] + g[w];
        s_sh[tid] = s;
        if (blockIdx.x == 0) g_s[tid] = s;
    }
    if (blockIdx.x == 0 && tid < CC) {
        g_sum[tid] = 0.f;
        g_sumsq[tid] = 0.f;
        float b = 0.f;
        for (int i = 0; i < 3; i++) b += gb[i * CC + tid];
        g_B[tid] = b;
    }
    __syncthreads();
    for (int idx = blockIdx.x * blockDim.x + tid; idx < NPAIR * CC * CC;
         idx += gridDim.x * blockDim.x) {
        int p = idx >> 12;
        int c = (idx >> 6) & 63;
        int o = idx & 63;
        int v0 = 2 * p, v1 = 2 * p + 1;
        float w0 = 0.f, w1 = 0.f;
        for (int i = 0; i < 3; i++) {
            float gv = gw[(i * CC + o) * CC + c];
            w0 += s_sh[i * 25 + v0] * gv;
            if (v1 < VV) w1 += s_sh[i * 25 + v1] * gv;
        }
        g_Wp[idx] = make_float2(w0, w1);
    }
}

// ---------------------------------------------------------------------------
// gemm<MODE>: block = (t-chunk, n). 416 threads = 13 warps.
// xs staged as [c][t*26 + v] (pad col 25 zeroed) so a vertex-pair x operand
// {x[c,t,2p], x[c,t,2p+1]} is one 8B-aligned LDS.64 broadcast.
// Warp-task = (vpair, o-half); lane owns o. Weight pairs live in registers
// (8-c chunks); inner loop = 16 LDS.64 + 16 FFMA2 per c, no barriers.
// MODE 0: per-lane stats -> smem atomics -> per-block global atomics.
// MODE 1: BN+residual folded into g_Wp2/g_B2; accs transposed through
//         hs[pos][o] (stride 65) -> coalesced relu stores.
// ---------------------------------------------------------------------------
template <int MODE>
__global__ void __launch_bounds__(NTHR, MODE ? 1 : 2)
gemm(const float* __restrict__ x, float* __restrict__ out) {
    extern __shared__ float smem[];
    float* xs = smem;
    float* aux = smem + CC * XROW;   // stats[128] (MODE0) or hs[400][65] (MODE1)
    int tid = threadIdx.x;
    int tc = blockIdx.x, n = blockIdx.y;

    if (MODE == 0 && tid < 128) aux[tid] = 0.f;
    // zero the dummy-vertex pad column (v=25) so pair 12's x.y is 0, not poison
    for (int e = tid; e < CC * TC; e += NTHR)
        xs[(e >> 4) * XROW + (e & 15) * 26 + 25] = 0.f;

    const float* src = x + (size_t)n * 409600 + tc * POS;
    for (int e = tid; e < CC * POS; e += NTHR) {
        int c = e / POS, r = e - c * POS;
        int t = r / 25, v = r - t * 25;
        xs[c * XROW + t * 26 + v] = src[c * 6400 + r];
    }
    __syncthreads();

    int warp = tid >> 5, lane = tid & 31;
    const ull* Wp = (const ull*)(MODE ? g_Wp2 : g_Wp);
    const float* Bv = MODE ? g_B2 : g_B;

    for (int task = warp; task < NTASK; task += NW) {
        int vp = task % NPAIR;
        int half = task / NPAIR;
        int o = half * 32 + lane;
        ull binit = packrep(Bv[o]);
        ull acc[TC];
#pragma unroll
        for (int t = 0; t < TC; t++) acc[t] = binit;

        const ull* wrow = Wp + (size_t)vp * 4096 + o;       // stride 64 per c
        const ull* xb = (const ull*)xs + vp;                // + c*208 + t*13
#pragma unroll 1
        for (int ch = 0; ch < 8; ch++) {
            ull w[8];
#pragma unroll
            for (int j = 0; j < 8; j++) w[j] = wrow[(ch * 8 + j) * 64];
#pragma unroll
            for (int j = 0; j < 8; j++) {
                const ull* xc = xb + (ch * 8 + j) * 208;
#pragma unroll
                for (int t = 0; t < TC; t++) ffma2(acc[t], w[j], xc[t * 13]);
            }
        }

        if (MODE == 0) {
            float s = 0.f, q = 0.f;
#pragma unroll
            for (int t = 0; t < TC; t++) {
                float h0, h1;
                unpack2(acc[t], h0, h1);
                s += h0; q += h0 * h0;
                if (vp != NPAIR - 1) { s += h1; q += h1 * h1; }
            }
            atomicAdd(&aux[o], s);
            atomicAdd(&aux[64 + o], q);
        } else {
#pragma unroll
            for (int t = 0; t < TC; t++) {
                float h0, h1;
                unpack2(acc[t], h0, h1);
                int pos = t * 25 + 2 * vp;
                aux[pos * HSTR + o] = h0;
                if (vp != NPAIR - 1) aux[(pos + 1) * HSTR + o] = h1;
            }
        }
    }
    __syncthreads();

    if (MODE == 0) {
        if (tid < 64) atomicAdd(&g_sum[tid], aux[tid]);
        else if (tid < 128) atomicAdd(&g_sumsq[tid - 64], aux[tid]);
    } else {
        float* dst = out + (size_t)n * 409600 + tc * POS;
        for (int e = tid; e < CC * POS; e += NTHR) {
            int o = e / POS, pos = e - o * POS;
            dst[o * 6400 + pos] = fmaxf(aux[pos * HSTR + o], 0.f);
        }
    }
}

// ---------------------------------------------------------------------------
// kbn_s: training-mode biased-var BN folded to per-channel scale/shift.
// ---------------------------------------------------------------------------
__global__ void kbn_s(const float* __restrict__ gamma, const float* __restrict__ beta) {
    int o = threadIdx.x;
    if (o < CC) {
        float m = g_sum[o] * (1.0f / NPOS);
        float var = g_sumsq[o] * (1.0f / NPOS) - m * m;
        float r = rsqrtf(var + 1e-5f);
        g_scale[o] = gamma[o] * r;
        g_shift[o] = beta[o] - m * gamma[o] * r;
    }
}

// ---------------------------------------------------------------------------
// kfold2: paired folded weights W2 = W*scale[o] + I (identity residual),
// dummy lane stays 0; B2 = B*scale + shift.
// ---------------------------------------------------------------------------
__global__ void kfold2(const float* __restrict__ gw) {
    __shared__ float s_sh[75];
    int tid = threadIdx.x;
    if (tid < 75) s_sh[tid] = g_s[tid];
    if (blockIdx.x == 0 && tid < CC)
        g_B2[tid] = g_B[tid] * g_scale[tid] + g_shift[tid];
    __syncthreads();
    for (int idx = blockIdx.x * blockDim.x + tid; idx < NPAIR * CC * CC;
         idx += gridDim.x * blockDim.x) {
        int p = idx >> 12;
        int c = (idx >> 6) & 63;
        int o = idx & 63;
        int v0 = 2 * p, v1 = 2 * p + 1;
        float w0 = 0.f, w1 = 0.f;
        for (int i = 0; i < 3; i++) {
            float gv = gw[(i * CC + o) * CC + c];
            w0 += s_sh[i * 25 + v0] * gv;
            if (v1 < VV) w1 += s_sh[i * 25 + v1] * gv;
        }
        float sc = g_scale[o];
        float id = (c == o) ? 1.f : 0.f;
        float a0 = w0 * sc + id;
        float a1 = (v1 < VV) ? (w1 * sc + id) : 0.f;
        g_Wp2[idx] = make_float2(a0, a1);
    }
}

extern "C" void kernel_launch(void* const* d_in, const int* in_sizes, int n_in,
                              void* d_out, int out_size) {
    const float* x     = (const float*)d_in[0];
    const float* A     = (const float*)d_in[1];
    const float* GA    = (const float*)d_in[2];
    const float* gw    = (const float*)d_in[7];
    const float* gb    = (const float*)d_in[8];
    const float* gamma = (const float*)d_in[9];
    const float* beta  = (const float*)d_in[10];
    float* out = (float*)d_out;
    (void)in_sizes; (void)n_in; (void)out_size;

    cudaFuncSetAttribute(gemm<0>, cudaFuncAttributeMaxDynamicSharedMemorySize, SM1);
    cudaFuncSetAttribute(gemm<1>, cudaFuncAttributeMaxDynamicSharedMemorySize, SM2);

    dim3 grid(TT / TC, NN);
    k0<<<52, 256>>>(A, GA, gw, gb);
    gemm<0><<<grid, NTHR, SM1>>>(x, out);
    kbn_s<<<1, 64>>>(gamma, beta);
    kfold2<<<52, 256>>>(gw);
    gemm<1><<<grid, NTHR, SM2>>>(x, out);
}

// round 5
// speedup vs baseline: 2.0978x; 1.3954x over previous
#include <cuda_runtime.h>

#define CC 64
#define TT 256
#define VV 25
#define NN 128
#define TC 8               /* t per block */
#define POS 200            /* TC*VV */
#define XROW 208           /* TC*26 padded floats per channel */
#define NPOS 819200.0f
#define NPAIR 13           /* vertex pairs; pair 12 = (24, dummy) */
#define NTHR 416           /* 13 warps */
#define HSTR 65
#define XS_FLOATS (CC * XROW)             /* 13312 floats = 53248 B */
#define SM1 (XS_FLOATS * 4 + 512)
#define SM2 (XS_FLOATS * 4 + POS * HSTR * 4)   /* 53248 + 52000 = 105248 */

typedef unsigned long long ull;

// Folded parameters / stats (device globals: no runtime allocation)
__device__ __align__(16) float2 g_Wp[NPAIR * CC * CC];   // [p][c][o] = {W[2p,c,o], W[2p+1,c,o]}
__device__ __align__(16) float2 g_Wp2[NPAIR * CC * CC];  // BN+identity-residual folded
__device__ __align__(16) float g_B[CC];
__device__ __align__(16) float g_B2[CC];
__device__ float g_s[3 * 25];
__device__ float g_sum[CC];
__device__ float g_sumsq[CC];

__device__ __forceinline__ void ffma2(ull& d, ull a, ull b) {
    asm("fma.rn.f32x2 %0, %1, %2, %0;" : "+l"(d) : "l"(a), "l"(b));
}
__device__ __forceinline__ ull packrep(float v) {
    ull r; asm("mov.b64 %0, {%1,%1};" : "=l"(r) : "f"(v)); return r;
}
__device__ __forceinline__ void unpack2(ull p, float& a, float& b) {
    asm("mov.b64 {%0,%1}, %2;" : "=f"(a), "=f"(b) : "l"(p));
}

// ---------------------------------------------------------------------------
// k0: softmax rows sum to 1 -> attention path collapses to s_i[v] =
// 1 + sum_w (A+GA)[i,v,w]. Build vertex-paired weights
// g_Wp[p][c][o] = {sum_i s_i[2p] gw[i,o,c], sum_i s_i[2p+1] gw[i,o,c]}.
// Also B, g_s, and zero the stat accumulators (graph replays).
// ---------------------------------------------------------------------------
__global__ void k0(const float* __restrict__ A, const float* __restrict__ GA,
                   const float* __restrict__ gw, const float* __restrict__ gb) {
    __shared__ float s_sh[75];
    int tid = threadIdx.x;
    if (tid < 75) {
        const float* a = A + tid * 25;
        const float* g = GA + tid * 25;
        float s = 1.f;
        for (int w = 0; w < 25; w++) s += a[w] + g[w];
        s_sh[tid] = s;
        if (blockIdx.x == 0) g_s[tid] = s;
    }
    if (blockIdx.x == 0 && tid < CC) {
        g_sum[tid] = 0.f;
        g_sumsq[tid] = 0.f;
        float b = 0.f;
        for (int i = 0; i < 3; i++) b += gb[i * CC + tid];
        g_B[tid] = b;
    }
    __syncthreads();
    for (int idx = blockIdx.x * blockDim.x + tid; idx < NPAIR * CC * CC;
         idx += gridDim.x * blockDim.x) {
        int p = idx >> 12;
        int c = (idx >> 6) & 63;
        int o = idx & 63;
        int v0 = 2 * p, v1 = 2 * p + 1;
        float w0 = 0.f, w1 = 0.f;
        for (int i = 0; i < 3; i++) {
            float gv = gw[(i * CC + o) * CC + c];
            w0 += s_sh[i * 25 + v0] * gv;
            if (v1 < VV) w1 += s_sh[i * 25 + v1] * gv;
        }
        g_Wp[idx] = make_float2(w0, w1);
    }
}

// ---------------------------------------------------------------------------
// gemm<MODE>: block = (t-chunk of 8, n). 416 threads = 13 warps, occupancy 2.
// xs staged as [c][t*26 + v] (pad col zeroed) so a vertex-pair x operand is
// one 8B LDS.64 broadcast. Warp = vertex pair; lane owns o=lane AND o=lane+32
// (one x load feeds both halves: 1 LDS : 2 FFMA2). Weights in registers,
// 4-channel chunks. acc = 2x8 packed f32x2 (32 regs) -> fits 78-reg cap.
// MODE 0: per-channel stats via smem atomics -> per-block global REDs.
// MODE 1: BN+residual pre-folded; accs -> hs[pos][65] -> coalesced relu store.
// ---------------------------------------------------------------------------
template <int MODE>
__global__ void __launch_bounds__(NTHR, 2)
gemm(const float* __restrict__ x, float* __restrict__ out) {
    extern __shared__ float smem[];
    float* xs = smem;
    float* aux = smem + XS_FLOATS;   // stats[128] (MODE0) or hs[200][65] (MODE1)
    int tid = threadIdx.x;
    int tc = blockIdx.x, n = blockIdx.y;

    if (MODE == 0 && tid < 128) aux[tid] = 0.f;
    for (int e = tid; e < CC * TC; e += NTHR)            // zero dummy-v pad
        xs[(e >> 3) * XROW + (e & 7) * 26 + 25] = 0.f;

    const float* src = x + (size_t)n * 409600 + tc * POS;
    for (int e = tid; e < CC * POS; e += NTHR) {
        int c = e / POS, r = e - c * POS;
        int t = r / 25, v = r - t * 25;
        xs[c * XROW + t * 26 + v] = src[c * 6400 + r];
    }
    __syncthreads();

    int warp = tid >> 5, lane = tid & 31;
    const ull* Wp = (const ull*)(MODE ? g_Wp2 : g_Wp);
    const float* Bv = MODE ? g_B2 : g_B;
    int vp = warp;                                       // 13 warps = 13 pairs

    ull acc0[TC], acc1[TC];
    {
        ull b0 = packrep(Bv[lane]);
        ull b1 = packrep(Bv[32 + lane]);
#pragma unroll
        for (int t = 0; t < TC; t++) { acc0[t] = b0; acc1[t] = b1; }
    }

    const ull* w0p = Wp + (size_t)vp * 4096 + lane;      // + c*64
    const ull* xb = (const ull*)xs + vp;                 // + c*104 + t*13
#pragma unroll 1
    for (int ch = 0; ch < 16; ch++) {                    // 4 channels per chunk
        ull w0[4], w1[4];
#pragma unroll
        for (int j = 0; j < 4; j++) {
            w0[j] = w0p[(ch * 4 + j) * 64];
            w1[j] = w0p[(ch * 4 + j) * 64 + 32];
        }
#pragma unroll
        for (int j = 0; j < 4; j++) {
            const ull* xc = xb + (ch * 4 + j) * 104;
#pragma unroll
            for (int t = 0; t < TC; t++) {
                ull xv = xc[t * 13];
                ffma2(acc0[t], w0[j], xv);
                ffma2(acc1[t], w1[j], xv);
            }
        }
    }

    if (MODE == 0) {
        float s0 = 0.f, q0 = 0.f, s1 = 0.f, q1 = 0.f;
#pragma unroll
        for (int t = 0; t < TC; t++) {
            float a, b;
            unpack2(acc0[t], a, b);
            s0 += a; q0 += a * a;
            if (vp != NPAIR - 1) { s0 += b; q0 += b * b; }
            unpack2(acc1[t], a, b);
            s1 += a; q1 += a * a;
            if (vp != NPAIR - 1) { s1 += b; q1 += b * b; }
        }
        atomicAdd(&aux[lane], s0);
        atomicAdd(&aux[64 + lane], q0);
        atomicAdd(&aux[32 + lane], s1);
        atomicAdd(&aux[96 + lane], q1);
        __syncthreads();
        if (tid < 64) atomicAdd(&g_sum[tid], aux[tid]);
        else if (tid < 128) atomicAdd(&g_sumsq[tid - 64], aux[tid]);
    } else {
#pragma unroll
        for (int t = 0; t < TC; t++) {
            float a, b;
            int pos = t * 25 + 2 * vp;
            unpack2(acc0[t], a, b);
            aux[pos * HSTR + lane] = a;
            if (vp != NPAIR - 1) aux[(pos + 1) * HSTR + lane] = b;
            unpack2(acc1[t], a, b);
            aux[pos * HSTR + 32 + lane] = a;
            if (vp != NPAIR - 1) aux[(pos + 1) * HSTR + 32 + lane] = b;
        }
        __syncthreads();
        float* dst = out + (size_t)n * 409600 + tc * POS;
        for (int e = tid; e < CC * POS; e += NTHR) {
            int o = e / POS, pos = e - o * POS;
            dst[o * 6400 + pos] = fmaxf(aux[pos * HSTR + o], 0.f);
        }
    }
}

// ---------------------------------------------------------------------------
// kfoldbn: fused BN-fold. Every block recomputes per-channel scale/shift from
// the global stats (cheap, 64 ch), block 0 writes B2, all blocks grid-stride
// the paired folded weights W2 = W*scale[o] + I (identity residual).
// ---------------------------------------------------------------------------
__global__ void kfoldbn(const float* __restrict__ gamma,
                        const float* __restrict__ beta,
                        const float* __restrict__ gw) {
    __shared__ float s_sh[75], sc_sh[64], sf_sh[64];
    int tid = threadIdx.x;
    if (tid < 75) s_sh[tid] = g_s[tid];
    if (tid < 64) {
        float m = g_sum[tid] * (1.0f / NPOS);
        float var = g_sumsq[tid] * (1.0f / NPOS) - m * m;
        float r = rsqrtf(var + 1e-5f);
        float sc = gamma[tid] * r;
        sc_sh[tid] = sc;
        sf_sh[tid] = beta[tid] - m * sc;
        if (blockIdx.x == 0) g_B2[tid] = g_B[tid] * sc + sf_sh[tid];
    }
    __syncthreads();
    for (int idx = blockIdx.x * blockDim.x + tid; idx < NPAIR * CC * CC;
         idx += gridDim.x * blockDim.x) {
        int p = idx >> 12;
        int c = (idx >> 6) & 63;
        int o = idx & 63;
        int v0 = 2 * p, v1 = 2 * p + 1;
        float w0 = 0.f, w1 = 0.f;
        for (int i = 0; i < 3; i++) {
            float gv = gw[(i * CC + o) * CC + c];
            w0 += s_sh[i * 25 + v0] * gv;
            if (v1 < VV) w1 += s_sh[i * 25 + v1] * gv;
        }
        float sc = sc_sh[o];
        float id = (c == o) ? 1.f : 0.f;
        g_Wp2[idx] = make_float2(w0 * sc + id, (v1 < VV) ? (w1 * sc + id) : 0.f);
    }
}

extern "C" void kernel_launch(void* const* d_in, const int* in_sizes, int n_in,
                              void* d_out, int out_size) {
    const float* x     = (const float*)d_in[0];
    const float* A     = (const float*)d_in[1];
    const float* GA    = (const float*)d_in[2];
    const float* gw    = (const float*)d_in[7];
    const float* gb    = (const float*)d_in[8];
    const float* gamma = (const float*)d_in[9];
    const float* beta  = (const float*)d_in[10];
    float* out = (float*)d_out;
    (void)in_sizes; (void)n_in; (void)out_size;

    cudaFuncSetAttribute(gemm<0>, cudaFuncAttributeMaxDynamicSharedMemorySize, SM1);
    cudaFuncSetAttribute(gemm<1>, cudaFuncAttributeMaxDynamicSharedMemorySize, SM2);

    dim3 grid(TT / TC, NN);                 // (32, 128) = 4096 blocks
    k0<<<52, 256>>>(A, GA, gw, gb);
    gemm<0><<<grid, NTHR, SM1>>>(x, out);
    kfoldbn<<<52, 256>>>(gamma, beta, gw);
    gemm<1><<<grid, NTHR, SM2>>>(x, out);   // in-set index 3 -> ncu lands here
}

// round 6
// speedup vs baseline: 2.2799x; 1.0868x over previous
#include <cuda_runtime.h>

#define CC 64
#define TT 256
#define VV 25
#define NN 128
#define TC 8               /* t per block */
#define POS 200            /* TC*VV */
#define XROW 208           /* TC*26 padded floats per channel */
#define NPOS 819200.0f
#define NPAIR 13           /* vertex pairs; pair 12 = (24, dummy) */
#define NTHR 416           /* 13 warps */
#define HSTR 65
#define XS_FLOATS (CC * XROW)          /* 13312 */
#define HS_FLOATS (POS * HSTR)         /* 13000 */
#define SMEMSZ ((XS_FLOATS + HS_FLOATS + 128) * 4)   /* 105760 B */
#define TOTEL 52428800     /* NN*CC*TT*VV */

typedef unsigned long long ull;

// Device globals (no runtime allocation)
__device__ __align__(16) ull g_Wq[NPAIR * CC * CC];  // [p][c][o4][og]: packed {W[2p,c,o],W[2p+1,c,o]}, o=og*16+o4
__device__ __align__(16) float g_B[CC];
__device__ float g_sum[CC];
__device__ float g_sumsq[CC];
__device__ float g_scale[CC];
__device__ float g_shift[CC];
__device__ float g_hid[TOTEL];                       // raw hidden, [n][o][t][v] (same layout as out)

__device__ __forceinline__ void ffma2(ull& d, ull a, ull b) {
    asm("fma.rn.f32x2 %0, %1, %2, %0;" : "+l"(d) : "l"(a), "l"(b));
}
__device__ __forceinline__ ull packrep(float v) {
    ull r; asm("mov.b64 %0, {%1,%1};" : "=l"(r) : "f"(v)); return r;
}
__device__ __forceinline__ void unpack2(ull p, float& a, float& b) {
    asm("mov.b64 {%0,%1}, %2;" : "=f"(a), "=f"(b) : "l"(p));
}

// ---------------------------------------------------------------------------
// k0: softmax rows sum to 1 -> attention collapses to s_i[v] = 1 + sum_w(A+GA).
// Build o-quad-interleaved paired weights:
//   g_Wq[((p*64+c)*16+o4)*4+og] = {sum_i s_i[2p] gw[i,o,c], sum_i s_i[2p+1] gw[i,o,c]},
//   o = og*16 + o4  (so one lane's 4 weights are 32 contiguous bytes).
// Also B = sum_i gb[i], zero stat accumulators (graph replays).
// ---------------------------------------------------------------------------
__global__ void k0(const float* __restrict__ A, const float* __restrict__ GA,
                   const float* __restrict__ gw, const float* __restrict__ gb) {
    __shared__ float s_sh[75];
    int tid = threadIdx.x;
    if (tid < 75) {
        const float* a = A + tid * 25;
        const float* g = GA + tid * 25;
        float s = 1.f;
        for (int w = 0; w < 25; w++) s += a[w] + g[w];
        s_sh[tid] = s;
    }
    if (blockIdx.x == 0 && tid < CC) {
        g_sum[tid] = 0.f;
        g_sumsq[tid] = 0.f;
        float b = 0.f;
        for (int i = 0; i < 3; i++) b += gb[i * CC + tid];
        g_B[tid] = b;
    }
    __syncthreads();
    for (int idx = blockIdx.x * blockDim.x + tid; idx < NPAIR * CC * CC;
         idx += gridDim.x * blockDim.x) {
        int og = idx & 3;
        int o4 = (idx >> 2) & 15;
        int c = (idx >> 6) & 63;
        int p = idx >> 12;
        int o = og * 16 + o4;
        int v0 = 2 * p, v1 = 2 * p + 1;
        float w0 = 0.f, w1 = 0.f;
        for (int i = 0; i < 3; i++) {
            float gv = gw[(i * CC + o) * CC + c];
            w0 += s_sh[i * 25 + v0] * gv;
            if (v1 < VV) w1 += s_sh[i * 25 + v1] * gv;
        }
        float2 pk = make_float2(w0, w1);
        g_Wq[idx] = *(ull*)&pk;
    }
}

// ---------------------------------------------------------------------------
// gemmst: the ONLY GEMM pass. Block=(tc,n), 13 warps, occupancy 2.
// Warp = vertex pair; lane = (o4 0..15, t-half). Each lane: 4 o's x 4 t's
// packed-f32x2 accs (32 regs). One broadcast LDS.64 of the x vertex-pair
// feeds 4 FFMA2; weights via 2 LDG.128 per channel (L2-resident).
// Epilogue: in-register stats -> smem -> global atomics, and raw hidden
// through conflict-free hs[pos][65] -> coalesced store to g_hid.
// ---------------------------------------------------------------------------
__global__ void __launch_bounds__(NTHR, 2)
gemmst(const float* __restrict__ x) {
    extern __shared__ float smem[];
    float* xs = smem;
    float* hs = smem + XS_FLOATS;
    float* aux = smem + XS_FLOATS + HS_FLOATS;   // stats[128]
    int tid = threadIdx.x;
    int tc = blockIdx.x, n = blockIdx.y;

    if (tid < 128) aux[tid] = 0.f;
    for (int e = tid; e < CC * TC; e += NTHR)    // zero dummy-vertex pad col
        xs[(e >> 3) * XROW + (e & 7) * 26 + 25] = 0.f;

    const float* src = x + (size_t)n * 409600 + tc * POS;
    for (int e = tid; e < CC * POS; e += NTHR) {
        int c = e / POS, r = e - c * POS;
        int t = r / 25, v = r - t * 25;
        xs[c * XROW + t * 26 + v] = src[c * 6400 + r];
    }
    __syncthreads();

    int vp = tid >> 5, lane = tid & 31;
    int o4 = lane & 15, th = lane >> 4;

    ull acc[4][4];                               // [og][tt]
#pragma unroll
    for (int og = 0; og < 4; og++) {
        ull b = packrep(g_B[og * 16 + o4]);
#pragma unroll
        for (int tt = 0; tt < 4; tt++) acc[og][tt] = b;
    }

    const ulonglong2* wq =
        (const ulonglong2*)(g_Wq + ((size_t)vp * 64) * 64 + o4 * 4);  // + c*32 (u2 units)
    const ull* xt = (const ull*)xs + vp + th * 52;                    // + c*104 + tt*13

#pragma unroll 1
    for (int ch = 0; ch < 32; ch++) {            // 2 channels per chunk
        int c0 = 2 * ch;
        ulonglong2 wA0 = wq[c0 * 32];
        ulonglong2 wA1 = wq[c0 * 32 + 1];
        ulonglong2 wB0 = wq[c0 * 32 + 32];
        ulonglong2 wB1 = wq[c0 * 32 + 33];
#pragma unroll
        for (int tt = 0; tt < 4; tt++) {
            ull xv = xt[c0 * 104 + tt * 13];
            ffma2(acc[0][tt], wA0.x, xv);
            ffma2(acc[1][tt], wA0.y, xv);
            ffma2(acc[2][tt], wA1.x, xv);
            ffma2(acc[3][tt], wA1.y, xv);
        }
#pragma unroll
        for (int tt = 0; tt < 4; tt++) {
            ull xv = xt[c0 * 104 + 104 + tt * 13];
            ffma2(acc[0][tt], wB0.x, xv);
            ffma2(acc[1][tt], wB0.y, xv);
            ffma2(acc[2][tt], wB1.x, xv);
            ffma2(acc[3][tt], wB1.y, xv);
        }
    }

    // stats + hs dump
    bool full = (vp != NPAIR - 1);
#pragma unroll
    for (int og = 0; og < 4; og++) {
        int o = og * 16 + o4;
        float s = 0.f, q = 0.f;
#pragma unroll
        for (int tt = 0; tt < 4; tt++) {
            float h0, h1;
            unpack2(acc[og][tt], h0, h1);
            s += h0; q += h0 * h0;
            int pos = (th * 4 + tt) * 25 + 2 * vp;
            hs[pos * HSTR + o] = h0;
            if (full) {
                s += h1; q += h1 * h1;
                hs[(pos + 1) * HSTR + o] = h1;
            }
        }
        atomicAdd(&aux[o], s);
        atomicAdd(&aux[64 + o], q);
    }
    __syncthreads();

    if (tid < 64) atomicAdd(&g_sum[tid], aux[tid]);
    else if (tid < 128) atomicAdd(&g_sumsq[tid - 64], aux[tid]);

    float* dst = g_hid + (size_t)n * 409600 + tc * POS;
    for (int e = tid; e < CC * POS; e += NTHR) {
        int o = e / POS, pos = e - o * POS;
        dst[o * 6400 + pos] = hs[pos * HSTR + o];
    }
}

// ---------------------------------------------------------------------------
// kbn: training-mode biased-var BN folded to per-channel scale/shift.
// ---------------------------------------------------------------------------
__global__ void kbn(const float* __restrict__ gamma, const float* __restrict__ beta) {
    int o = threadIdx.x;
    if (o < CC) {
        float m = g_sum[o] * (1.0f / NPOS);
        float var = g_sumsq[o] * (1.0f / NPOS) - m * m;
        float r = rsqrtf(var + 1e-5f);
        float sc = gamma[o] * r;
        g_scale[o] = sc;
        g_shift[o] = beta[o] - m * sc;
    }
}

// ---------------------------------------------------------------------------
// epi: pure streaming epilogue. out = relu(hid*scale[o] + shift[o] + x).
// float4 grid-stride; hid layout == x/out layout so o = (i/1600) & 63 is
// constant within each float4. 600 MB total traffic, fully coalesced.
// ---------------------------------------------------------------------------
__global__ void __launch_bounds__(256) epi(const float* __restrict__ x,
                                           float* __restrict__ out) {
    __shared__ float sc_sh[64], sf_sh[64];
    int tid = threadIdx.x;
    if (tid < 64) { sc_sh[tid] = g_scale[tid]; sf_sh[tid] = g_shift[tid]; }
    __syncthreads();
    const float4* h4 = (const float4*)g_hid;
    const float4* x4 = (const float4*)x;
    float4* o4p = (float4*)out;
    int stride = gridDim.x * 256;
    for (int i = blockIdx.x * 256 + tid; i < TOTEL / 4; i += stride) {
        int o = (i / 1600) & 63;
        float sc = sc_sh[o], sf = sf_sh[o];
        float4 h = h4[i], xv = x4[i], r;
        r.x = fmaxf(fmaf(h.x, sc, sf) + xv.x, 0.f);
        r.y = fmaxf(fmaf(h.y, sc, sf) + xv.y, 0.f);
        r.z = fmaxf(fmaf(h.z, sc, sf) + xv.z, 0.f);
        r.w = fmaxf(fmaf(h.w, sc, sf) + xv.w, 0.f);
        o4p[i] = r;
    }
}

extern "C" void kernel_launch(void* const* d_in, const int* in_sizes, int n_in,
                              void* d_out, int out_size) {
    const float* x     = (const float*)d_in[0];
    const float* A     = (const float*)d_in[1];
    const float* GA    = (const float*)d_in[2];
    const float* gw    = (const float*)d_in[7];
    const float* gb    = (const float*)d_in[8];
    const float* gamma = (const float*)d_in[9];
    const float* beta  = (const float*)d_in[10];
    float* out = (float*)d_out;
    (void)in_sizes; (void)n_in; (void)out_size;

    cudaFuncSetAttribute(gemmst, cudaFuncAttributeMaxDynamicSharedMemorySize, SMEMSZ);

    k0<<<52, 256>>>(A, GA, gw, gb);
    gemmst<<<dim3(TT / TC, NN), NTHR, SMEMSZ>>>(x);
    kbn<<<1, 64>>>(gamma, beta);
    epi<<<4096, 256>>>(x, out);
}

// round 7
// speedup vs baseline: 2.4719x; 1.0842x over previous
#include <cuda_runtime.h>

#define CC 64
#define TT 256
#define VV 25
#define NN 128
#define TC 8               /* t per block */
#define POS 200            /* TC*VV */
#define XROW 208           /* TC*26 padded floats per channel */
#define NPOS 819200.0f
#define NPAIR 13           /* vertex pairs; pair 12 = (24, dummy) */
#define NTHR 416           /* 13 warps */
#define HSTR 65
#define XS_FLOATS (CC * XROW)          /* 13312 */
#define HS_FLOATS (POS * HSTR)         /* 13000 */
#define SMEMSZ ((XS_FLOATS + HS_FLOATS + 128) * 4)   /* 105760 B */
#define TOTEL 52428800     /* NN*CC*TT*VV */

typedef unsigned long long ull;

// Device globals (no runtime allocation). g_Wq padded +64 so the mainloop's
// one-channel-ahead prefetch never faults on the last iteration.
__device__ __align__(16) ull g_Wq[NPAIR * CC * CC + 64];
__device__ __align__(16) float g_B[CC];
__device__ float g_sum[CC];
__device__ float g_sumsq[CC];
__device__ float g_scale[CC];
__device__ float g_shift[CC];
__device__ float g_hid[TOTEL];         // raw hidden, [n][o][t][v] (same layout as out)

__device__ __forceinline__ void ffma2(ull& d, ull a, ull b) {
    asm("fma.rn.f32x2 %0, %1, %2, %0;" : "+l"(d) : "l"(a), "l"(b));
}
__device__ __forceinline__ ull packrep(float v) {
    ull r; asm("mov.b64 %0, {%1,%1};" : "=l"(r) : "f"(v)); return r;
}
__device__ __forceinline__ void unpack2(ull p, float& a, float& b) {
    asm("mov.b64 {%0,%1}, %2;" : "=f"(a), "=f"(b) : "l"(p));
}

// ---------------------------------------------------------------------------
// k0: softmax rows sum to 1 -> attention collapses to s_i[v] = 1 + sum_w(A+GA).
// Quad-interleaved paired weights:
//   g_Wq[((p*64+c)*16+o4)*4+og] = {sum_i s_i[2p] gw[i,o,c], sum_i s_i[2p+1] gw[i,o,c]},
//   o = og*16 + o4  (one lane's 4 weights = 32 contiguous bytes).
// Also B = sum_i gb[i]; zero stat accumulators (graph replays).
// ---------------------------------------------------------------------------
__global__ void k0(const float* __restrict__ A, const float* __restrict__ GA,
                   const float* __restrict__ gw, const float* __restrict__ gb) {
    __shared__ float s_sh[75];
    int tid = threadIdx.x;
    if (tid < 75) {
        const float* a = A + tid * 25;
        const float* g = GA + tid * 25;
        float s = 1.f;
        for (int w = 0; w < 25; w++) s += a[w] + g[w];
        s_sh[tid] = s;
    }
    if (blockIdx.x == 0 && tid < CC) {
        g_sum[tid] = 0.f;
        g_sumsq[tid] = 0.f;
        float b = 0.f;
        for (int i = 0; i < 3; i++) b += gb[i * CC + tid];
        g_B[tid] = b;
    }
    __syncthreads();
    for (int idx = blockIdx.x * blockDim.x + tid; idx < NPAIR * CC * CC;
         idx += gridDim.x * blockDim.x) {
        int og = idx & 3;
        int o4 = (idx >> 2) & 15;
        int c = (idx >> 6) & 63;
        int p = idx >> 12;
        int o = og * 16 + o4;
        int v0 = 2 * p, v1 = 2 * p + 1;
        float w0 = 0.f, w1 = 0.f;
        for (int i = 0; i < 3; i++) {
            float gv = gw[(i * CC + o) * CC + c];
            w0 += s_sh[i * 25 + v0] * gv;
            if (v1 < VV) w1 += s_sh[i * 25 + v1] * gv;
        }
        float2 pk = make_float2(w0, w1);
        g_Wq[idx] = *(ull*)&pk;
    }
}

// ---------------------------------------------------------------------------
// gemmst: single GEMM pass. Block=(tc,n), 13 warps, occupancy 2.
// Warp = vertex pair; lane = (o4 0..15, t-half). Lane computes 4 o's x 4 t's
// as packed-f32x2 accs (32 regs). One broadcast LDS.64 feeds 4 FFMA2.
// Weights software-pipelined one channel ahead (2 LDG.128 prefetch while the
// current channel's 16 FFMA2 issue) -> no exposed L2 latency, ~62 live regs.
// Epilogue: in-register stats -> smem -> global atomics; hidden via
// conflict-free hs[pos][65] transpose -> coalesced division-free store.
// ---------------------------------------------------------------------------
__global__ void __launch_bounds__(NTHR, 2)
gemmst(const float* __restrict__ x) {
    extern __shared__ float smem[];
    float* xs = smem;
    float* hs = smem + XS_FLOATS;
    float* aux = smem + XS_FLOATS + HS_FLOATS;   // stats[128]
    int tid = threadIdx.x;
    int tc = blockIdx.x, n = blockIdx.y;

    if (tid < 128) aux[tid] = 0.f;
    // zero the dummy-vertex pad column (v=25)
    for (int e = tid; e < CC * TC; e += NTHR)
        xs[(e >> 3) * XROW + (e & 7) * 26 + 25] = 0.f;

    // division-free staging: thread owns fixed r=(t,v), walks 32 channels
    {
        const float* src = x + (size_t)n * 409600 + tc * POS;
        int act = (tid < 400);
        int r = act ? ((tid < 200) ? tid : tid - 200) : 0;
        int cbase = (tid < 200) ? 0 : 32;
        int t = r / 25, v = r - t * 25;          // computed once
        int sx = t * 26 + v;
        if (act) {
#pragma unroll 4
            for (int cc = 0; cc < 32; cc++) {
                int c = cbase + cc;
                xs[c * XROW + sx] = src[c * 6400 + r];
            }
        }
    }
    __syncthreads();

    int vp = tid >> 5, lane = tid & 31;
    int o4 = lane & 15, th = lane >> 4;

    ull acc[4][4];                               // [og][tt]
#pragma unroll
    for (int og = 0; og < 4; og++) {
        ull b = packrep(g_B[og * 16 + o4]);
#pragma unroll
        for (int tt = 0; tt < 4; tt++) acc[og][tt] = b;
    }

    const ulonglong2* wq =
        (const ulonglong2*)(g_Wq) + (size_t)vp * 2048 + o4 * 2;  // + c*32
    const ull* xt = (const ull*)xs + vp + th * 52;               // + c*104 + tt*13

    ulonglong2 w0 = wq[0], w1 = wq[1];           // channel 0
#pragma unroll 2
    for (int c = 0; c < CC; c++) {
        ulonglong2 n0 = wq[(c + 1) * 32];        // prefetch next channel
        ulonglong2 n1 = wq[(c + 1) * 32 + 1];    // (padded: never faults)
#pragma unroll
        for (int tt = 0; tt < 4; tt++) {
            ull xv = xt[c * 104 + tt * 13];
            ffma2(acc[0][tt], w0.x, xv);
            ffma2(acc[1][tt], w0.y, xv);
            ffma2(acc[2][tt], w1.x, xv);
            ffma2(acc[3][tt], w1.y, xv);
        }
        w0 = n0; w1 = n1;
    }

    // stats + hs transpose dump
    bool full = (vp != NPAIR - 1);
#pragma unroll
    for (int og = 0; og < 4; og++) {
        int o = og * 16 + o4;
        float s = 0.f, q = 0.f;
#pragma unroll
        for (int tt = 0; tt < 4; tt++) {
            float h0, h1;
            unpack2(acc[og][tt], h0, h1);
            s += h0; q += h0 * h0;
            int pos = (th * 4 + tt) * 25 + 2 * vp;
            hs[pos * HSTR + o] = h0;
            if (full) {
                s += h1; q += h1 * h1;
                hs[(pos + 1) * HSTR + o] = h1;
            }
        }
        atomicAdd(&aux[o], s);
        atomicAdd(&aux[64 + o], q);
    }
    __syncthreads();

    if (tid < 64) atomicAdd(&g_sum[tid], aux[tid]);
    else if (tid < 128) atomicAdd(&g_sumsq[tid - 64], aux[tid]);

    // division-free coalesced store: thread owns fixed pos, walks 32 channels
    if (tid < 400) {
        int half = (tid >= 200);
        int pos = tid - half * 200;
        float* dst = g_hid + (size_t)n * 409600 + tc * POS + pos + half * 32 * 6400;
        const float* hrow = hs + pos * HSTR + half * 32;
#pragma unroll 4
        for (int oo = 0; oo < 32; oo++)
            dst[oo * 6400] = hrow[oo];
    }
}

// ---------------------------------------------------------------------------
// kbn: training-mode biased-var BN folded to per-channel scale/shift.
// ---------------------------------------------------------------------------
__global__ void kbn(const float* __restrict__ gamma, const float* __restrict__ beta) {
    int o = threadIdx.x;
    if (o < CC) {
        float m = g_sum[o] * (1.0f / NPOS);
        float var = g_sumsq[o] * (1.0f / NPOS) - m * m;
        float r = rsqrtf(var + 1e-5f);
        float sc = gamma[o] * r;
        g_scale[o] = sc;
        g_shift[o] = beta[o] - m * sc;
    }
}

// ---------------------------------------------------------------------------
// epi: streaming epilogue (measured 83.8% of DRAM peak — near roofline).
// out = relu(hid*scale[o] + shift[o] + x), float4 grid-stride.
// ---------------------------------------------------------------------------
__global__ void __launch_bounds__(256) epi(const float* __restrict__ x,
                                           float* __restrict__ out) {
    __shared__ float sc_sh[64], sf_sh[64];
    int tid = threadIdx.x;
    if (tid < 64) { sc_sh[tid] = g_scale[tid]; sf_sh[tid] = g_shift[tid]; }
    __syncthreads();
    const float4* h4 = (const float4*)g_hid;
    const float4* x4 = (const float4*)x;
    float4* o4p = (float4*)out;
    int stride = gridDim.x * 256;
    for (int i = blockIdx.x * 256 + tid; i < TOTEL / 4; i += stride) {
        int o = (i / 1600) & 63;
        float sc = sc_sh[o], sf = sf_sh[o];
        float4 h = h4[i], xv = x4[i], r;
        r.x = fmaxf(fmaf(h.x, sc, sf) + xv.x, 0.f);
        r.y = fmaxf(fmaf(h.y, sc, sf) + xv.y, 0.f);
        r.z = fmaxf(fmaf(h.z, sc, sf) + xv.z, 0.f);
        r.w = fmaxf(fmaf(h.w, sc, sf) + xv.w, 0.f);
        o4p[i] = r;
    }
}

extern "C" void kernel_launch(void* const* d_in, const int* in_sizes, int n_in,
                              void* d_out, int out_size) {
    const float* x     = (const float*)d_in[0];
    const float* A     = (const float*)d_in[1];
    const float* GA    = (const float*)d_in[2];
    const float* gw    = (const float*)d_in[7];
    const float* gb    = (const float*)d_in[8];
    const float* gamma = (const float*)d_in[9];
    const float* beta  = (const float*)d_in[10];
    float* out = (float*)d_out;
    (void)in_sizes; (void)n_in; (void)out_size;

    cudaFuncSetAttribute(gemmst, cudaFuncAttributeMaxDynamicSharedMemorySize, SMEMSZ);

    k0<<<52, 256>>>(A, GA, gw, gb);
    gemmst<<<dim3(TT / TC, NN), NTHR, SMEMSZ>>>(x);
    kbn<<<1, 64>>>(gamma, beta);
    epi<<<4096, 256>>>(x, out);
}